// round 1
// baseline (speedup 1.0000x reference)
#include <cuda_runtime.h>
#include <cstdint>

#define BATCH 8
#define CDIM 64
#define NDIM 110592                 // 48*48*48
#define CN (CDIM*NDIM)

#define CHUNK 2048
#define NCHK (NDIM/CHUNK)           // 54
#define GBLOCKS (BATCH*NCHK)        // 432
#define KK 32

#define TILE3 512
#define SUB 64

// scratch (no cudaMalloc allowed)
__device__ float g_partial[GBLOCKS][CDIM*CDIM];   // 432*4096*4 = 7.08 MB
__device__ float g_aff[BATCH][CDIM*CDIM];         // sigmoid(G@G)

__device__ __forceinline__ uint32_t f2tf32(float f) {
    uint32_t r;
    asm("cvt.rna.tf32.f32 %0, %1;" : "=r"(r) : "f"(f));
    return r;
}

__device__ __forceinline__ void mma_tf32(float& d0, float& d1, float& d2, float& d3,
                                         uint32_t a0, uint32_t a1, uint32_t a2, uint32_t a3,
                                         uint32_t b0, uint32_t b1) {
    asm volatile("mma.sync.aligned.m16n8k8.row.col.f32.tf32.tf32.f32 "
                 "{%0,%1,%2,%3}, {%4,%5,%6,%7}, {%8,%9}, {%0,%1,%2,%3};"
                 : "+f"(d0), "+f"(d1), "+f"(d2), "+f"(d3)
                 : "r"(a0), "r"(a1), "r"(a2), "r"(a3), "r"(b0), "r"(b1));
}

// ---------------------------------------------------------------------------
// Pass 1: partial Gram. Each block: G_part[64][64] over a 2048-wide n-chunk.
// ---------------------------------------------------------------------------
__global__ __launch_bounds__(256) void gram_kernel(const float* __restrict__ x) {
    int b = blockIdx.x / NCHK;
    int chunk = blockIdx.x % NCHK;
    const float* xb = x + (size_t)b * CN + (size_t)chunk * CHUNK;

    __shared__ float tile[CDIM][KK + 4];   // stride 36 -> conflict-free frag loads

    int tid = threadIdx.x;
    int lane = tid & 31, warp = tid >> 5;
    int gid = lane >> 2, tg = lane & 3;
    int m0 = (warp & 3) * 16;       // 4 m-slabs of 16
    int n0 = (warp >> 2) * 32;      // 2 n-slabs of 32

    float acc[4][4];
#pragma unroll
    for (int t = 0; t < 4; t++)
#pragma unroll
        for (int i = 0; i < 4; i++) acc[t][i] = 0.f;

    int lrow = tid >> 3;            // 0..31 (8 threads per row: full 128B line)
    int lcol = (tid & 7) * 4;

    for (int it = 0; it < CHUNK / KK; it++) {
        const float* src = xb + it * KK;
        float4 v0 = *(const float4*)(src + (size_t)lrow * NDIM + lcol);
        float4 v1 = *(const float4*)(src + (size_t)(lrow + 32) * NDIM + lcol);
        __syncthreads();            // previous tile fully consumed
        *(float4*)&tile[lrow][lcol] = v0;
        *(float4*)&tile[lrow + 32][lcol] = v1;
        __syncthreads();
#pragma unroll
        for (int ks = 0; ks < KK / 8; ks++) {
            int k = ks * 8;
            uint32_t a0 = f2tf32(tile[m0 + gid][k + tg]);
            uint32_t a1 = f2tf32(tile[m0 + 8 + gid][k + tg]);
            uint32_t a2 = f2tf32(tile[m0 + gid][k + 4 + tg]);
            uint32_t a3 = f2tf32(tile[m0 + 8 + gid][k + 4 + tg]);
#pragma unroll
            for (int t = 0; t < 4; t++) {
                uint32_t b0v = f2tf32(tile[n0 + t * 8 + gid][k + tg]);
                uint32_t b1v = f2tf32(tile[n0 + t * 8 + gid][k + 4 + tg]);
                mma_tf32(acc[t][0], acc[t][1], acc[t][2], acc[t][3],
                         a0, a1, a2, a3, b0v, b1v);
            }
        }
    }

    float* gp = g_partial[blockIdx.x];
#pragma unroll
    for (int t = 0; t < 4; t++) {
        int cc = n0 + t * 8 + tg * 2;
        gp[(m0 + gid) * CDIM + cc]         = acc[t][0];
        gp[(m0 + gid) * CDIM + cc + 1]     = acc[t][1];
        gp[(m0 + 8 + gid) * CDIM + cc]     = acc[t][2];
        gp[(m0 + 8 + gid) * CDIM + cc + 1] = acc[t][3];
    }
}

// ---------------------------------------------------------------------------
// Pass 2: reduce partials -> G, m3 = G@G, affinity = sigmoid(m3). 1 block/batch.
// ---------------------------------------------------------------------------
__global__ __launch_bounds__(256) void affinity_kernel() {
    int b = blockIdx.x;
    __shared__ float Gs[CDIM][CDIM + 1];
    int tid = threadIdx.x;

    for (int idx = tid; idx < CDIM * CDIM; idx += 256) {
        float s = 0.f;
        for (int j = 0; j < NCHK; j++)
            s += g_partial[b * NCHK + j][idx];
        Gs[idx >> 6][idx & 63] = s;
    }
    __syncthreads();

    for (int idx = tid; idx < CDIM * CDIM; idx += 256) {
        int r = idx >> 6, c = idx & 63;
        float s = 0.f;
#pragma unroll 8
        for (int d = 0; d < CDIM; d++)
            s += Gs[r][d] * Gs[d][c];
        // sigmoid; saturates cleanly for |s| huge (expf -> 0 or inf)
        g_aff[b][idx] = 1.f / (1.f + expf(-s));
    }
}

// ---------------------------------------------------------------------------
// Pass 3: out = gamma * (Aff @ K) + x. x tile serves as MMA B operand AND addend.
// ---------------------------------------------------------------------------
__global__ __launch_bounds__(256) void apply_kernel(const float* __restrict__ x,
                                                    const float* __restrict__ gamma_p,
                                                    float* __restrict__ out) {
    int b = blockIdx.x / (NDIM / TILE3);
    int tblk = blockIdx.x % (NDIM / TILE3);
    size_t base = (size_t)b * CN;
    const float* xb = x + base + (size_t)tblk * TILE3;
    float* ob = out + base + (size_t)tblk * TILE3;
    float gamma = *gamma_p;

    __shared__ float As[CDIM][CDIM + 4];   // affinity, stride 68
    __shared__ float Ks[CDIM][SUB + 4];    // x tile (rows = channel d), stride 68

    int tid = threadIdx.x;
    int lane = tid & 31, warp = tid >> 5;
    int gid = lane >> 2, tg = lane & 3;
    int m0 = (warp & 3) * 16;
    int n0w = (warp >> 2) * 32;

    const float* aff = g_aff[b];
    for (int idx = tid; idx < CDIM * CDIM; idx += 256)
        As[idx >> 6][idx & 63] = aff[idx];
    __syncthreads();

    // A fragments (affinity) reused across all 8 subtiles: preconvert once.
    uint32_t afr[8][4];
#pragma unroll
    for (int ks = 0; ks < 8; ks++) {
        int k = ks * 8;
        afr[ks][0] = f2tf32(As[m0 + gid][k + tg]);
        afr[ks][1] = f2tf32(As[m0 + 8 + gid][k + tg]);
        afr[ks][2] = f2tf32(As[m0 + gid][k + 4 + tg]);
        afr[ks][3] = f2tf32(As[m0 + 8 + gid][k + 4 + tg]);
    }

    int lrow8 = tid >> 4;            // 0..15 (16 threads cover a 64-float row)
    int lcol = (tid & 15) * 4;

    for (int sub = 0; sub < TILE3 / SUB; sub++) {
        const float* src = xb + sub * SUB;
        float4 v[4];
#pragma unroll
        for (int rr = 0; rr < 4; rr++)
            v[rr] = *(const float4*)(src + (size_t)(lrow8 + rr * 16) * NDIM + lcol);
        __syncthreads();             // epilogue reads of previous subtile done
#pragma unroll
        for (int rr = 0; rr < 4; rr++)
            *(float4*)&Ks[lrow8 + rr * 16][lcol] = v[rr];
        __syncthreads();

        float acc[4][4];
#pragma unroll
        for (int t = 0; t < 4; t++)
#pragma unroll
            for (int i = 0; i < 4; i++) acc[t][i] = 0.f;

#pragma unroll
        for (int ks = 0; ks < 8; ks++) {
            int k = ks * 8;
#pragma unroll
            for (int t = 0; t < 4; t++) {
                uint32_t b0v = f2tf32(Ks[k + tg][n0w + t * 8 + gid]);
                uint32_t b1v = f2tf32(Ks[k + 4 + tg][n0w + t * 8 + gid]);
                mma_tf32(acc[t][0], acc[t][1], acc[t][2], acc[t][3],
                         afr[ks][0], afr[ks][1], afr[ks][2], afr[ks][3], b0v, b1v);
            }
        }

        // epilogue: out[c, n] = gamma*acc + x[c, n]  (x addend read from Ks)
        int nbase = sub * SUB;
#pragma unroll
        for (int t = 0; t < 4; t++) {
            int cc = n0w + t * 8 + tg * 2;
            int r0 = m0 + gid, r1 = m0 + 8 + gid;
            float2 k0 = *(float2*)&Ks[r0][cc];
            float2 k1 = *(float2*)&Ks[r1][cc];
            float2 o0 = make_float2(fmaf(gamma, acc[t][0], k0.x), fmaf(gamma, acc[t][1], k0.y));
            float2 o1 = make_float2(fmaf(gamma, acc[t][2], k1.x), fmaf(gamma, acc[t][3], k1.y));
            *(float2*)(ob + (size_t)r0 * NDIM + nbase + cc) = o0;
            *(float2*)(ob + (size_t)r1 * NDIM + nbase + cc) = o1;
        }
    }
}

extern "C" void kernel_launch(void* const* d_in, const int* in_sizes, int n_in,
                              void* d_out, int out_size) {
    (void)in_sizes; (void)n_in; (void)out_size;
    const float* x = (const float*)d_in[0];
    const float* gamma = (const float*)d_in[1];
    float* out = (float*)d_out;

    gram_kernel<<<GBLOCKS, 256>>>(x);
    affinity_kernel<<<BATCH, 256>>>();
    apply_kernel<<<BATCH * (NDIM / TILE3), 256>>>(x, gamma, out);
}

// round 2
// speedup vs baseline: 1.0855x; 1.0855x over previous
#include <cuda_runtime.h>
#include <cstdint>

#define BATCH 8
#define CDIM 64
#define NDIM 110592                 // 48*48*48
#define CN (CDIM*NDIM)

#define CHUNK 2048
#define NCHK (NDIM/CHUNK)           // 54
#define GBLOCKS (BATCH*NCHK)        // 432
#define NIT (CHUNK/64)              // 32

#define TILE3 512
#define SUB 64
#define NSUB (TILE3/SUB)            // 8

// scratch (no cudaMalloc allowed)
__device__ float g_partial[GBLOCKS][CDIM*CDIM];   // 7.08 MB
__device__ float g_aff[BATCH][CDIM*CDIM];

__device__ __forceinline__ uint32_t f2tf32(float f) {
    uint32_t r;
    asm("cvt.rna.tf32.f32 %0, %1;" : "=r"(r) : "f"(f));
    return r;
}
__device__ __forceinline__ uint32_t packbf(float lo, float hi) {
    uint32_t r;   // PTX: d, a, b  -> a goes to upper half, b to lower half
    asm("cvt.rn.satfinite.bf16x2.f32 %0, %1, %2;" : "=r"(r) : "f"(hi), "f"(lo));
    return r;
}

__device__ __forceinline__ void mma_bf16(float* d,
                                         uint32_t a0, uint32_t a1, uint32_t a2, uint32_t a3,
                                         uint32_t b0, uint32_t b1) {
    asm volatile("mma.sync.aligned.m16n8k16.row.col.f32.bf16.bf16.f32 "
                 "{%0,%1,%2,%3}, {%4,%5,%6,%7}, {%8,%9}, {%0,%1,%2,%3};"
                 : "+f"(d[0]), "+f"(d[1]), "+f"(d[2]), "+f"(d[3])
                 : "r"(a0), "r"(a1), "r"(a2), "r"(a3), "r"(b0), "r"(b1));
}
__device__ __forceinline__ void mma_tf32(float* d,
                                         uint32_t a0, uint32_t a1, uint32_t a2, uint32_t a3,
                                         uint32_t b0, uint32_t b1) {
    asm volatile("mma.sync.aligned.m16n8k8.row.col.f32.tf32.tf32.f32 "
                 "{%0,%1,%2,%3}, {%4,%5,%6,%7}, {%8,%9}, {%0,%1,%2,%3};"
                 : "+f"(d[0]), "+f"(d[1]), "+f"(d[2]), "+f"(d[3])
                 : "r"(a0), "r"(a1), "r"(a2), "r"(a3), "r"(b0), "r"(b1));
}

// ---------------------------------------------------------------------------
// Pass 1: partial Gram with bf16 m16n8k16 MMA, K=64 slabs, double-buffered.
// smem rows: 36 uint32 pairs = 72 bf16 = 144B stride (conflict-free frags).
// ---------------------------------------------------------------------------
__global__ __launch_bounds__(256) void gram_kernel(const float* __restrict__ x) {
    int b = blockIdx.x / NCHK;
    int chunk = blockIdx.x % NCHK;
    const float* xb = x + (size_t)b * CN + (size_t)chunk * CHUNK;

    __shared__ uint32_t tile[2][CDIM][36];

    int tid = threadIdx.x;
    int lane = tid & 31, warp = tid >> 5;
    int gid = lane >> 2, tg = lane & 3;
    int m0 = (warp & 3) * 16;
    int n0 = (warp >> 2) * 32;

    int lrow = tid >> 2;               // 0..63
    int cb = (tid & 3) * 4;            // col base within 64
    const float* rowp = xb + (size_t)lrow * NDIM + cb;
    int pbase = (tid & 3) * 2;         // pair index base

    float acc[4][4];
#pragma unroll
    for (int t = 0; t < 4; t++)
#pragma unroll
        for (int i = 0; i < 4; i++) acc[t][i] = 0.f;

    float4 v[4];

#pragma unroll
    for (int i = 0; i < 4; i++) v[i] = *(const float4*)(rowp + 16 * i);
#pragma unroll
    for (int i = 0; i < 4; i++) {
        uint32_t p0 = packbf(v[i].x, v[i].y);
        uint32_t p1 = packbf(v[i].z, v[i].w);
        *(uint2*)&tile[0][lrow][pbase + 8 * i] = make_uint2(p0, p1);
    }
    __syncthreads();

    for (int it = 0; it < NIT; it++) {
        if (it + 1 < NIT) {
            const float* src = rowp + (it + 1) * 64;
#pragma unroll
            for (int i = 0; i < 4; i++) v[i] = *(const float4*)(src + 16 * i);
        }
        // compute on tile[it&1]
        {
            const uint32_t (*T)[36] = tile[it & 1];
#pragma unroll
            for (int s = 0; s < 4; s++) {
                int pa = 8 * s + tg;
                uint32_t a0 = T[m0 + gid][pa];
                uint32_t a1 = T[m0 + 8 + gid][pa];
                uint32_t a2 = T[m0 + gid][pa + 4];
                uint32_t a3 = T[m0 + 8 + gid][pa + 4];
#pragma unroll
                for (int t = 0; t < 4; t++) {
                    uint32_t b0 = T[n0 + t * 8 + gid][pa];
                    uint32_t b1 = T[n0 + t * 8 + gid][pa + 4];
                    mma_bf16(acc[t], a0, a1, a2, a3, b0, b1);
                }
            }
        }
        __syncthreads();
        if (it + 1 < NIT) {
            int bi = (it + 1) & 1;
#pragma unroll
            for (int i = 0; i < 4; i++) {
                uint32_t p0 = packbf(v[i].x, v[i].y);
                uint32_t p1 = packbf(v[i].z, v[i].w);
                *(uint2*)&tile[bi][lrow][pbase + 8 * i] = make_uint2(p0, p1);
            }
        }
        __syncthreads();
    }

    float* gp = g_partial[blockIdx.x];
#pragma unroll
    for (int t = 0; t < 4; t++) {
        int cc = n0 + t * 8 + tg * 2;
        gp[(m0 + gid) * CDIM + cc]         = acc[t][0];
        gp[(m0 + gid) * CDIM + cc + 1]     = acc[t][1];
        gp[(m0 + 8 + gid) * CDIM + cc]     = acc[t][2];
        gp[(m0 + 8 + gid) * CDIM + cc + 1] = acc[t][3];
    }
}

// ---------------------------------------------------------------------------
// Pass 2: reduce partials -> G, m3 = G@G, affinity = sigmoid(m3). 1 block/batch.
// ---------------------------------------------------------------------------
__global__ __launch_bounds__(256) void affinity_kernel() {
    int b = blockIdx.x;
    __shared__ float Gs[CDIM][CDIM + 1];
    int tid = threadIdx.x;

    float s[16];
#pragma unroll
    for (int u = 0; u < 16; u++) s[u] = 0.f;
    for (int j = 0; j < NCHK; j++) {
        const float* gp = g_partial[b * NCHK + j];
#pragma unroll
        for (int u = 0; u < 16; u++) s[u] += gp[tid + 256 * u];
    }
#pragma unroll
    for (int u = 0; u < 16; u++) {
        int idx = tid + 256 * u;
        Gs[idx >> 6][idx & 63] = s[u];
    }
    __syncthreads();

    for (int idx = tid; idx < CDIM * CDIM; idx += 256) {
        int r = idx >> 6, c = idx & 63;
        float acc = 0.f;
#pragma unroll 8
        for (int d = 0; d < CDIM; d++)
            acc += Gs[r][d] * Gs[d][c];
        g_aff[b][idx] = 1.f / (1.f + expf(-acc));
    }
}

// ---------------------------------------------------------------------------
// Pass 3: out = gamma * (Aff @ K) + x.
// tf32 MMA with raw-f32-bit B operands (no cvt in inner loop); A fragments
// pre-converted once into registers; register-prefetch double-buffer flow.
// Xs row stride = 72 floats -> B-fragment LDS conflict-free.
// ---------------------------------------------------------------------------
__global__ __launch_bounds__(256) void apply_kernel(const float* __restrict__ x,
                                                    const float* __restrict__ gamma_p,
                                                    float* __restrict__ out) {
    int b = blockIdx.x / (NDIM / TILE3);
    int tblk = blockIdx.x % (NDIM / TILE3);
    size_t base = (size_t)b * CN;
    const float* xb = x + base + (size_t)tblk * TILE3;
    float* ob = out + base + (size_t)tblk * TILE3;
    float gamma = *gamma_p;

    __shared__ float As[CDIM][CDIM + 1];
    __shared__ float Xs[CDIM][72];

    int tid = threadIdx.x;
    int lane = tid & 31, warp = tid >> 5;
    int gid = lane >> 2, tg = lane & 3;
    int m0 = (warp & 3) * 16;
    int n0w = (warp >> 2) * 32;

    const float* aff = g_aff[b];
    for (int idx = tid; idx < CDIM * CDIM; idx += 256)
        As[idx >> 6][idx & 63] = aff[idx];
    __syncthreads();

    // A fragments for all 8 k-slices, converted once.
    uint32_t afr[8][4];
#pragma unroll
    for (int ks = 0; ks < 8; ks++) {
        int k = ks * 8;
        afr[ks][0] = f2tf32(As[m0 + gid][k + tg]);
        afr[ks][1] = f2tf32(As[m0 + 8 + gid][k + tg]);
        afr[ks][2] = f2tf32(As[m0 + gid][k + 4 + tg]);
        afr[ks][3] = f2tf32(As[m0 + 8 + gid][k + 4 + tg]);
    }

    int lrow = tid >> 2;               // 0..63
    int cb = (tid & 3) * 4;
    const float* rowp = xb + (size_t)lrow * NDIM + cb;

    float4 v[4];
#pragma unroll
    for (int i = 0; i < 4; i++) v[i] = *(const float4*)(rowp + 16 * i);
#pragma unroll
    for (int i = 0; i < 4; i++) *(float4*)&Xs[lrow][cb + 16 * i] = v[i];
    __syncthreads();

    for (int sub = 0; sub < NSUB; sub++) {
        if (sub + 1 < NSUB) {
            const float* src = rowp + (sub + 1) * SUB;
#pragma unroll
            for (int i = 0; i < 4; i++) v[i] = *(const float4*)(src + 16 * i);
        }

        float acc[4][4];
#pragma unroll
        for (int t = 0; t < 4; t++)
#pragma unroll
            for (int i = 0; i < 4; i++) acc[t][i] = 0.f;

#pragma unroll
        for (int ks = 0; ks < 8; ks++) {
            int k = ks * 8;
#pragma unroll
            for (int t = 0; t < 4; t++) {
                uint32_t b0v = __float_as_uint(Xs[k + tg][n0w + t * 8 + gid]);
                uint32_t b1v = __float_as_uint(Xs[k + 4 + tg][n0w + t * 8 + gid]);
                mma_tf32(acc[t], afr[ks][0], afr[ks][1], afr[ks][2], afr[ks][3], b0v, b1v);
            }
        }

        // epilogue: out = gamma*acc + x  (exact f32 addend from Xs)
        int nbase = sub * SUB;
#pragma unroll
        for (int t = 0; t < 4; t++) {
            int cc = n0w + t * 8 + tg * 2;
            int r0 = m0 + gid, r1 = m0 + 8 + gid;
            float2 k0 = *(float2*)&Xs[r0][cc];
            float2 k1 = *(float2*)&Xs[r1][cc];
            float2 o0 = make_float2(fmaf(gamma, acc[t][0], k0.x), fmaf(gamma, acc[t][1], k0.y));
            float2 o1 = make_float2(fmaf(gamma, acc[t][2], k1.x), fmaf(gamma, acc[t][3], k1.y));
            *(float2*)(ob + (size_t)r0 * NDIM + nbase + cc) = o0;
            *(float2*)(ob + (size_t)r1 * NDIM + nbase + cc) = o1;
        }
        __syncthreads();          // all reads of Xs (MMA + addend) complete
        if (sub + 1 < NSUB) {
#pragma unroll
            for (int i = 0; i < 4; i++) *(float4*)&Xs[lrow][cb + 16 * i] = v[i];
        }
        __syncthreads();
    }
}

extern "C" void kernel_launch(void* const* d_in, const int* in_sizes, int n_in,
                              void* d_out, int out_size) {
    (void)in_sizes; (void)n_in; (void)out_size;
    const float* x = (const float*)d_in[0];
    const float* gamma = (const float*)d_in[1];
    float* out = (float*)d_out;

    gram_kernel<<<GBLOCKS, 256>>>(x);
    affinity_kernel<<<BATCH, 256>>>();
    apply_kernel<<<BATCH * (NDIM / TILE3), 256>>>(x, gamma, out);
}

// round 4
// speedup vs baseline: 1.3049x; 1.2021x over previous
#include <cuda_runtime.h>
#include <cstdint>

#define BATCH 8
#define CDIM 64
#define NDIM 110592                 // 48*48*48
#define CN (CDIM*NDIM)

#define CHUNK 2048
#define NCHK (NDIM/CHUNK)           // 54
#define GBLOCKS (BATCH*NCHK)        // 432
#define NIT (CHUNK/64)              // 32

#define TILE3 512
#define SUB 64
#define NSUB (TILE3/SUB)            // 8

// scratch (no cudaMalloc allowed)
__device__ float    g_partial[GBLOCKS][CDIM*CDIM];   // 7.08 MB
__device__ uint32_t g_affp[BATCH][CDIM*32];          // packed bf16-pair affinity [c][pd]

__device__ __forceinline__ uint32_t packbf(float lo, float hi) {
    uint32_t r;   // PTX operand order: d, a(hi), b(lo)
    asm("cvt.rn.satfinite.bf16x2.f32 %0, %1, %2;" : "=r"(r) : "f"(hi), "f"(lo));
    return r;
}

__device__ __forceinline__ void mma_bf16(float* d,
                                         uint32_t a0, uint32_t a1, uint32_t a2, uint32_t a3,
                                         uint32_t b0, uint32_t b1) {
    asm volatile("mma.sync.aligned.m16n8k16.row.col.f32.bf16.bf16.f32 "
                 "{%0,%1,%2,%3}, {%4,%5,%6,%7}, {%8,%9}, {%0,%1,%2,%3};"
                 : "+f"(d[0]), "+f"(d[1]), "+f"(d[2]), "+f"(d[3])
                 : "r"(a0), "r"(a1), "r"(a2), "r"(a3), "r"(b0), "r"(b1));
}

// ---------------------------------------------------------------------------
// Pass 1: partial Gram with bf16 m16n8k16 MMA, K=64 slabs, double-buffered.
// ---------------------------------------------------------------------------
__global__ __launch_bounds__(256) void gram_kernel(const float* __restrict__ x) {
    int b = blockIdx.x / NCHK;
    int chunk = blockIdx.x % NCHK;
    const float* xb = x + (size_t)b * CN + (size_t)chunk * CHUNK;

    __shared__ uint32_t tile[2][CDIM][36];

    int tid = threadIdx.x;
    int lane = tid & 31, warp = tid >> 5;
    int gid = lane >> 2, tg = lane & 3;
    int m0 = (warp & 3) * 16;
    int n0 = (warp >> 2) * 32;

    int lrow = tid >> 2;
    int cb = (tid & 3) * 4;
    const float* rowp = xb + (size_t)lrow * NDIM + cb;
    int pbase = (tid & 3) * 2;

    float acc[4][4];
#pragma unroll
    for (int t = 0; t < 4; t++)
#pragma unroll
        for (int i = 0; i < 4; i++) acc[t][i] = 0.f;

    float4 v[4];
#pragma unroll
    for (int i = 0; i < 4; i++) v[i] = *(const float4*)(rowp + 16 * i);
#pragma unroll
    for (int i = 0; i < 4; i++) {
        uint32_t p0 = packbf(v[i].x, v[i].y);
        uint32_t p1 = packbf(v[i].z, v[i].w);
        *(uint2*)&tile[0][lrow][pbase + 8 * i] = make_uint2(p0, p1);
    }
    __syncthreads();

    for (int it = 0; it < NIT; it++) {
        if (it + 1 < NIT) {
            const float* src = rowp + (it + 1) * 64;
#pragma unroll
            for (int i = 0; i < 4; i++) v[i] = *(const float4*)(src + 16 * i);
        }
        {
            const uint32_t (*T)[36] = tile[it & 1];
#pragma unroll
            for (int s = 0; s < 4; s++) {
                int pa = 8 * s + tg;
                uint32_t a0 = T[m0 + gid][pa];
                uint32_t a1 = T[m0 + 8 + gid][pa];
                uint32_t a2 = T[m0 + gid][pa + 4];
                uint32_t a3 = T[m0 + 8 + gid][pa + 4];
#pragma unroll
                for (int t = 0; t < 4; t++) {
                    uint32_t b0 = T[n0 + t * 8 + gid][pa];
                    uint32_t b1 = T[n0 + t * 8 + gid][pa + 4];
                    mma_bf16(acc[t], a0, a1, a2, a3, b0, b1);
                }
            }
        }
        __syncthreads();
        if (it + 1 < NIT) {
            int bi = (it + 1) & 1;
#pragma unroll
            for (int i = 0; i < 4; i++) {
                uint32_t p0 = packbf(v[i].x, v[i].y);
                uint32_t p1 = packbf(v[i].z, v[i].w);
                *(uint2*)&tile[bi][lrow][pbase + 8 * i] = make_uint2(p0, p1);
            }
        }
        __syncthreads();
    }

    float* gp = g_partial[blockIdx.x];
#pragma unroll
    for (int t = 0; t < 4; t++) {
        int cc = n0 + t * 8 + tg * 2;
        gp[(m0 + gid) * CDIM + cc]         = acc[t][0];
        gp[(m0 + gid) * CDIM + cc + 1]     = acc[t][1];
        gp[(m0 + 8 + gid) * CDIM + cc]     = acc[t][2];
        gp[(m0 + 8 + gid) * CDIM + cc + 1] = acc[t][3];
    }
}

// ---------------------------------------------------------------------------
// Pass 2: reduce partials -> G, m3 = G@G, affinity = sigmoid(m3),
// emitted PRE-PACKED as bf16 pairs along d: g_affp[b][c][pd].
// ---------------------------------------------------------------------------
__global__ __launch_bounds__(256) void affinity_kernel() {
    int b = blockIdx.x;
    __shared__ float Gs[CDIM][CDIM + 1];
    int tid = threadIdx.x;

    float s[16];
#pragma unroll
    for (int u = 0; u < 16; u++) s[u] = 0.f;
    for (int j = 0; j < NCHK; j++) {
        const float* gp = g_partial[b * NCHK + j];
#pragma unroll
        for (int u = 0; u < 16; u++) s[u] += gp[tid + 256 * u];
    }
#pragma unroll
    for (int u = 0; u < 16; u++) {
        int idx = tid + 256 * u;
        Gs[idx >> 6][idx & 63] = s[u];
    }
    __syncthreads();

    // thread handles row r = tid>>2, 16 consecutive cols c0..c0+15
    int r = tid >> 2;
    int c0 = (tid & 3) * 16;
    float vals[16];
#pragma unroll
    for (int j = 0; j < 16; j++) {
        float acc = 0.f;
#pragma unroll 8
        for (int d = 0; d < CDIM; d++)
            acc += Gs[r][d] * Gs[d][c0 + j];
        vals[j] = 1.f / (1.f + expf(-acc));
    }
    uint32_t pw[8];
#pragma unroll
    for (int j = 0; j < 8; j++) pw[j] = packbf(vals[2 * j], vals[2 * j + 1]);
    uint32_t* dst = &g_affp[b][r * 32 + (tid & 3) * 8];
    *(uint4*)(dst)     = make_uint4(pw[0], pw[1], pw[2], pw[3]);
    *(uint4*)(dst + 4) = make_uint4(pw[4], pw[5], pw[6], pw[7]);
}

// ---------------------------------------------------------------------------
// Pass 3: out = gamma * (Aff @ K) + x.  bf16 m16n8k16.
// A fragments: packed affinity straight from global (L2-hot).
// B: packed x-pair tile P[pd][n], 64 cols, stride 72 -> conflict-free reads
//    (bank = tg*8 + gid, all lanes distinct).
// Addend: exact f32 x re-read from gmem (L1-resident from loader).
// ---------------------------------------------------------------------------
__global__ __launch_bounds__(256) void apply_kernel(const float* __restrict__ x,
                                                    const float* __restrict__ gamma_p,
                                                    float* __restrict__ out) {
    int b = blockIdx.x / (NDIM / TILE3);
    int tblk = blockIdx.x % (NDIM / TILE3);
    size_t base = (size_t)b * CN;
    const float* xb = x + base + (size_t)tblk * TILE3;
    float* ob = out + base + (size_t)tblk * TILE3;
    float gamma = *gamma_p;

    __shared__ uint32_t P[32][72];      // bf16 pairs along channel d, 64 n-cols

    int tid = threadIdx.x;
    int lane = tid & 31, warp = tid >> 5;
    int gid = lane >> 2, tg = lane & 3;
    int m0 = (warp & 3) * 16;
    int n0w = (warp >> 2) * 32;

    // A fragments (packed bf16 affinity) from global: 16 LDG.32, L2-broadcast
    const uint32_t* PA = g_affp[b];
    uint32_t afr[4][4];
#pragma unroll
    for (int s = 0; s < 4; s++) {
        int pa = s * 8 + tg;
        afr[s][0] = PA[(m0 + gid) * 32 + pa];
        afr[s][1] = PA[(m0 + 8 + gid) * 32 + pa];
        afr[s][2] = PA[(m0 + gid) * 32 + pa + 4];
        afr[s][3] = PA[(m0 + 8 + gid) * 32 + pa + 4];
    }

    // loader: thread covers pair-row pr (rows 2pr,2pr+1), 8 cols at cg*8
    int pr = tid >> 3;                  // 0..31
    int cg = tid & 7;                   // 0..7
    const float* row0 = xb + (size_t)(2 * pr) * NDIM + cg * 8;
    const float* row1 = row0 + NDIM;

    float4 u0, u1, w0, w1;
    u0 = *(const float4*)(row0);
    u1 = *(const float4*)(row0 + 4);
    w0 = *(const float4*)(row1);
    w1 = *(const float4*)(row1 + 4);
    {
        uint4 p0 = make_uint4(packbf(u0.x, w0.x), packbf(u0.y, w0.y),
                              packbf(u0.z, w0.z), packbf(u0.w, w0.w));
        uint4 p1 = make_uint4(packbf(u1.x, w1.x), packbf(u1.y, w1.y),
                              packbf(u1.z, w1.z), packbf(u1.w, w1.w));
        // pair = (x[2pr][n], x[2pr+1][n]) -> lo = even row, hi = odd row
        *(uint4*)&P[pr][cg * 8]     = p0;
        *(uint4*)&P[pr][cg * 8 + 4] = p1;
    }
    __syncthreads();

    for (int sub = 0; sub < NSUB; sub++) {
        if (sub + 1 < NSUB) {
            const float* s0 = row0 + (sub + 1) * SUB;
            const float* s1 = row1 + (sub + 1) * SUB;
            u0 = *(const float4*)(s0);
            u1 = *(const float4*)(s0 + 4);
            w0 = *(const float4*)(s1);
            w1 = *(const float4*)(s1 + 4);
        }

        float acc[4][4];
#pragma unroll
        for (int t = 0; t < 4; t++)
#pragma unroll
            for (int i = 0; i < 4; i++) acc[t][i] = 0.f;

#pragma unroll
        for (int s = 0; s < 4; s++) {
            int pa = s * 8 + tg;
#pragma unroll
            for (int t = 0; t < 4; t++) {
                int n = n0w + t * 8 + gid;
                uint32_t b0 = P[pa][n];
                uint32_t b1 = P[pa + 4][n];
                mma_bf16(acc[t], afr[s][0], afr[s][1], afr[s][2], afr[s][3], b0, b1);
            }
        }

        // epilogue: out = gamma*acc + x (exact f32 addend from gmem, L1-hot)
        int nbase = sub * SUB;
#pragma unroll
        for (int t = 0; t < 4; t++) {
            int cc = nbase + n0w + t * 8 + tg * 2;
            int r0 = m0 + gid, r1 = r0 + 8;
            float2 x0 = *(const float2*)(xb + (size_t)r0 * NDIM + cc);
            float2 x1 = *(const float2*)(xb + (size_t)r1 * NDIM + cc);
            float2 o0 = make_float2(fmaf(gamma, acc[t][0], x0.x), fmaf(gamma, acc[t][1], x0.y));
            float2 o1 = make_float2(fmaf(gamma, acc[t][2], x1.x), fmaf(gamma, acc[t][3], x1.y));
            *(float2*)(ob + (size_t)r0 * NDIM + cc) = o0;
            *(float2*)(ob + (size_t)r1 * NDIM + cc) = o1;
        }

        if (sub + 1 < NSUB) {
            __syncthreads();        // all P reads done
            uint4 p0 = make_uint4(packbf(u0.x, w0.x), packbf(u0.y, w0.y),
                                  packbf(u0.z, w0.z), packbf(u0.w, w0.w));
            uint4 p1 = make_uint4(packbf(u1.x, w1.x), packbf(u1.y, w1.y),
                                  packbf(u1.z, w1.z), packbf(u1.w, w1.w));
            *(uint4*)&P[pr][cg * 8]     = p0;
            *(uint4*)&P[pr][cg * 8 + 4] = p1;
            __syncthreads();
        }
    }
}

extern "C" void kernel_launch(void* const* d_in, const int* in_sizes, int n_in,
                              void* d_out, int out_size) {
    (void)in_sizes; (void)n_in; (void)out_size;
    const float* x = (const float*)d_in[0];
    const float* gamma = (const float*)d_in[1];
    float* out = (float*)d_out;

    gram_kernel<<<GBLOCKS, 256>>>(x);
    affinity_kernel<<<BATCH, 256>>>();
    apply_kernel<<<BATCH * (NDIM / TILE3), 256>>>(x, gamma, out);
}

// round 6
// speedup vs baseline: 1.3176x; 1.0098x over previous
#include <cuda_runtime.h>
#include <cstdint>

#define BATCH 8
#define CDIM 64
#define NDIM 110592                 // 48*48*48
#define CN (CDIM*NDIM)

#define CHUNK 2048
#define NCHK (NDIM/CHUNK)           // 54
#define GBLOCKS (BATCH*NCHK)        // 432
#define NIT (CHUNK/64)              // 32

#define TILE3 1024
#define SUB 64
#define NSUB (TILE3/SUB)            // 16

// scratch (no cudaMalloc allowed)
__device__ float    g_partial[GBLOCKS][CDIM*CDIM];   // 7.08 MB
__device__ uint32_t g_affp[BATCH][CDIM*32];          // packed bf16-pair affinity [c][pd]

__device__ __forceinline__ uint32_t packbf(float lo, float hi) {
    uint32_t r;   // PTX operand order: d, a(hi), b(lo)
    asm("cvt.rn.satfinite.bf16x2.f32 %0, %1, %2;" : "=r"(r) : "f"(hi), "f"(lo));
    return r;
}

__device__ __forceinline__ void mma_bf16(float* d,
                                         uint32_t a0, uint32_t a1, uint32_t a2, uint32_t a3,
                                         uint32_t b0, uint32_t b1) {
    asm volatile("mma.sync.aligned.m16n8k16.row.col.f32.bf16.bf16.f32 "
                 "{%0,%1,%2,%3}, {%4,%5,%6,%7}, {%8,%9}, {%0,%1,%2,%3};"
                 : "+f"(d[0]), "+f"(d[1]), "+f"(d[2]), "+f"(d[3])
                 : "r"(a0), "r"(a1), "r"(a2), "r"(a3), "r"(b0), "r"(b1));
}

// ---------------------------------------------------------------------------
// Pass 1: partial Gram with bf16 m16n8k16 MMA, K=64 slabs, double-buffered.
// (unchanged from R4 — 53.9us measured)
// ---------------------------------------------------------------------------
__global__ __launch_bounds__(256) void gram_kernel(const float* __restrict__ x) {
    int b = blockIdx.x / NCHK;
    int chunk = blockIdx.x % NCHK;
    const float* xb = x + (size_t)b * CN + (size_t)chunk * CHUNK;

    __shared__ uint32_t tile[2][CDIM][36];

    int tid = threadIdx.x;
    int lane = tid & 31, warp = tid >> 5;
    int gid = lane >> 2, tg = lane & 3;
    int m0 = (warp & 3) * 16;
    int n0 = (warp >> 2) * 32;

    int lrow = tid >> 2;
    int cb = (tid & 3) * 4;
    const float* rowp = xb + (size_t)lrow * NDIM + cb;
    int pbase = (tid & 3) * 2;

    float acc[4][4];
#pragma unroll
    for (int t = 0; t < 4; t++)
#pragma unroll
        for (int i = 0; i < 4; i++) acc[t][i] = 0.f;

    float4 v[4];
#pragma unroll
    for (int i = 0; i < 4; i++) v[i] = *(const float4*)(rowp + 16 * i);
#pragma unroll
    for (int i = 0; i < 4; i++) {
        uint32_t p0 = packbf(v[i].x, v[i].y);
        uint32_t p1 = packbf(v[i].z, v[i].w);
        *(uint2*)&tile[0][lrow][pbase + 8 * i] = make_uint2(p0, p1);
    }
    __syncthreads();

    for (int it = 0; it < NIT; it++) {
        if (it + 1 < NIT) {
            const float* src = rowp + (it + 1) * 64;
#pragma unroll
            for (int i = 0; i < 4; i++) v[i] = *(const float4*)(src + 16 * i);
        }
        {
            const uint32_t (*T)[36] = tile[it & 1];
#pragma unroll
            for (int s = 0; s < 4; s++) {
                int pa = 8 * s + tg;
                uint32_t a0 = T[m0 + gid][pa];
                uint32_t a1 = T[m0 + 8 + gid][pa];
                uint32_t a2 = T[m0 + gid][pa + 4];
                uint32_t a3 = T[m0 + 8 + gid][pa + 4];
#pragma unroll
                for (int t = 0; t < 4; t++) {
                    uint32_t b0 = T[n0 + t * 8 + gid][pa];
                    uint32_t b1 = T[n0 + t * 8 + gid][pa + 4];
                    mma_bf16(acc[t], a0, a1, a2, a3, b0, b1);
                }
            }
        }
        __syncthreads();
        if (it + 1 < NIT) {
            int bi = (it + 1) & 1;
#pragma unroll
            for (int i = 0; i < 4; i++) {
                uint32_t p0 = packbf(v[i].x, v[i].y);
                uint32_t p1 = packbf(v[i].z, v[i].w);
                *(uint2*)&tile[bi][lrow][pbase + 8 * i] = make_uint2(p0, p1);
            }
        }
        __syncthreads();
    }

    float* gp = g_partial[blockIdx.x];
#pragma unroll
    for (int t = 0; t < 4; t++) {
        int cc = n0 + t * 8 + tg * 2;
        gp[(m0 + gid) * CDIM + cc]         = acc[t][0];
        gp[(m0 + gid) * CDIM + cc + 1]     = acc[t][1];
        gp[(m0 + 8 + gid) * CDIM + cc]     = acc[t][2];
        gp[(m0 + 8 + gid) * CDIM + cc + 1] = acc[t][3];
    }
}

// ---------------------------------------------------------------------------
// Pass 2: reduce partials -> G, m3 = G@G, affinity = sigmoid(m3),
// emitted PRE-PACKED as bf16 pairs along d: g_affp[b][c][pd].
// ---------------------------------------------------------------------------
__global__ __launch_bounds__(256) void affinity_kernel() {
    int b = blockIdx.x;
    __shared__ float Gs[CDIM][CDIM + 1];
    int tid = threadIdx.x;

    float s[16];
#pragma unroll
    for (int u = 0; u < 16; u++) s[u] = 0.f;
    for (int j = 0; j < NCHK; j++) {
        const float* gp = g_partial[b * NCHK + j];
#pragma unroll
        for (int u = 0; u < 16; u++) s[u] += gp[tid + 256 * u];
    }
#pragma unroll
    for (int u = 0; u < 16; u++) {
        int idx = tid + 256 * u;
        Gs[idx >> 6][idx & 63] = s[u];
    }
    __syncthreads();

    int r = tid >> 2;
    int c0 = (tid & 3) * 16;
    float vals[16];
#pragma unroll
    for (int j = 0; j < 16; j++) {
        float acc = 0.f;
#pragma unroll 8
        for (int d = 0; d < CDIM; d++)
            acc += Gs[r][d] * Gs[d][c0 + j];
        vals[j] = 1.f / (1.f + expf(-acc));
    }
    uint32_t pw[8];
#pragma unroll
    for (int j = 0; j < 8; j++) pw[j] = packbf(vals[2 * j], vals[2 * j + 1]);
    uint32_t* dst = &g_affp[b][r * 32 + (tid & 3) * 8];
    *(uint4*)(dst)     = make_uint4(pw[0], pw[1], pw[2], pw[3]);
    *(uint4*)(dst + 4) = make_uint4(pw[4], pw[5], pw[6], pw[7]);
}

// ---------------------------------------------------------------------------
// Pass 3: out = gamma * (Aff @ K) + x.  bf16 m16n8k16.
// Warp covers m32 x n16 -> each B fragment feeds 2 m-slabs (half the B-LDS).
// A fragments (all 32 regs) from packed affinity in global, loaded once.
// Addend x prefetched into registers BEFORE the MMA section (L2 latency hidden).
// P[pd][n]: 64 n-cols, stride 72 -> conflict-free fragment reads.
// ---------------------------------------------------------------------------
__global__ __launch_bounds__(256) void apply_kernel(const float* __restrict__ x,
                                                    const float* __restrict__ gamma_p,
                                                    float* __restrict__ out) {
    int b = blockIdx.x / (NDIM / TILE3);
    int tblk = blockIdx.x % (NDIM / TILE3);
    size_t base = (size_t)b * CN;
    const float* xb = x + base + (size_t)tblk * TILE3;
    float* ob = out + base + (size_t)tblk * TILE3;
    float gamma = *gamma_p;

    __shared__ uint32_t P[32][72];      // bf16 pairs along channel d, 64 n-cols

    int tid = threadIdx.x;
    int lane = tid & 31, warp = tid >> 5;
    int gid = lane >> 2, tg = lane & 3;
    int m0 = (warp & 1) * 32;           // warp's 32-channel slab
    int n0w = (warp >> 1) * 16;         // warp's 16-col slice

    // A fragments: 2 m-slabs x 4 k-slabs x 4 regs, from global (L2-broadcast)
    const uint32_t* PA = g_affp[b];
    uint32_t afr[2][4][4];
#pragma unroll
    for (int mi = 0; mi < 2; mi++) {
        int mr = m0 + 16 * mi + gid;
#pragma unroll
        for (int s = 0; s < 4; s++) {
            int pa = s * 8 + tg;
            afr[mi][s][0] = PA[mr * 32 + pa];
            afr[mi][s][1] = PA[(mr + 8) * 32 + pa];
            afr[mi][s][2] = PA[mr * 32 + pa + 4];
            afr[mi][s][3] = PA[(mr + 8) * 32 + pa + 4];
        }
    }

    // loader: thread covers pair-row pr (rows 2pr,2pr+1), 8 cols at cg*8
    int pr = tid >> 3;                  // 0..31
    int cg = tid & 7;                   // 0..7
    const float* row0 = xb + (size_t)(2 * pr) * NDIM + cg * 8;
    const float* row1 = row0 + NDIM;

    float4 u0, u1, w0, w1;
    u0 = *(const float4*)(row0);
    u1 = *(const float4*)(row0 + 4);
    w0 = *(const float4*)(row1);
    w1 = *(const float4*)(row1 + 4);
    {
        uint4 p0 = make_uint4(packbf(u0.x, w0.x), packbf(u0.y, w0.y),
                              packbf(u0.z, w0.z), packbf(u0.w, w0.w));
        uint4 p1 = make_uint4(packbf(u1.x, w1.x), packbf(u1.y, w1.y),
                              packbf(u1.z, w1.z), packbf(u1.w, w1.w));
        *(uint4*)&P[pr][cg * 8]     = p0;
        *(uint4*)&P[pr][cg * 8 + 4] = p1;
    }
    __syncthreads();

    for (int sub = 0; sub < NSUB; sub++) {
        int nbase = sub * SUB;

        // (1) prefetch this sub's f32 addend into regs (independent of MMA)
        float2 xadd[2][2][2];           // [mi][half][t]
#pragma unroll
        for (int mi = 0; mi < 2; mi++)
#pragma unroll
            for (int h = 0; h < 2; h++) {
                int r = m0 + 16 * mi + 8 * h + gid;
#pragma unroll
                for (int t = 0; t < 2; t++) {
                    int cc = nbase + n0w + t * 8 + tg * 2;
                    xadd[mi][h][t] = *(const float2*)(xb + (size_t)r * NDIM + cc);
                }
            }

        // (2) prefetch next tile for the loader role
        if (sub + 1 < NSUB) {
            const float* s0 = row0 + (sub + 1) * SUB;
            const float* s1 = row1 + (sub + 1) * SUB;
            u0 = *(const float4*)(s0);
            u1 = *(const float4*)(s0 + 4);
            w0 = *(const float4*)(s1);
            w1 = *(const float4*)(s1 + 4);
        }

        // (3) MMA: 16 mmas; each B fragment pair shared by both m-slabs
        float acc[2][2][4];
#pragma unroll
        for (int mi = 0; mi < 2; mi++)
#pragma unroll
            for (int t = 0; t < 2; t++)
#pragma unroll
                for (int i = 0; i < 4; i++) acc[mi][t][i] = 0.f;

#pragma unroll
        for (int s = 0; s < 4; s++) {
            int pa = s * 8 + tg;
#pragma unroll
            for (int t = 0; t < 2; t++) {
                int n = n0w + t * 8 + gid;
                uint32_t b0 = P[pa][n];
                uint32_t b1 = P[pa + 4][n];
                mma_bf16(acc[0][t], afr[0][s][0], afr[0][s][1], afr[0][s][2], afr[0][s][3], b0, b1);
                mma_bf16(acc[1][t], afr[1][s][0], afr[1][s][1], afr[1][s][2], afr[1][s][3], b0, b1);
            }
        }

        // (4) epilogue: out = gamma*acc + x (addend already in regs)
#pragma unroll
        for (int mi = 0; mi < 2; mi++)
#pragma unroll
            for (int t = 0; t < 2; t++) {
                int cc = nbase + n0w + t * 8 + tg * 2;
                int r0 = m0 + 16 * mi + gid, r1 = r0 + 8;
                float2 o0 = make_float2(fmaf(gamma, acc[mi][t][0], xadd[mi][0][t].x),
                                        fmaf(gamma, acc[mi][t][1], xadd[mi][0][t].y));
                float2 o1 = make_float2(fmaf(gamma, acc[mi][t][2], xadd[mi][1][t].x),
                                        fmaf(gamma, acc[mi][t][3], xadd[mi][1][t].y));
                *(float2*)(ob + (size_t)r0 * NDIM + cc) = o0;
                *(float2*)(ob + (size_t)r1 * NDIM + cc) = o1;
            }

        if (sub + 1 < NSUB) {
            __syncthreads();        // all P reads done
            uint4 p0 = make_uint4(packbf(u0.x, w0.x), packbf(u0.y, w0.y),
                                  packbf(u0.z, w0.z), packbf(u0.w, w0.w));
            uint4 p1 = make_uint4(packbf(u1.x, w1.x), packbf(u1.y, w1.y),
                                  packbf(u1.z, w1.z), packbf(u1.w, w1.w));
            *(uint4*)&P[pr][cg * 8]     = p0;
            *(uint4*)&P[pr][cg * 8 + 4] = p1;
            __syncthreads();
        }
    }
}

extern "C" void kernel_launch(void* const* d_in, const int* in_sizes, int n_in,
                              void* d_out, int out_size) {
    (void)in_sizes; (void)n_in; (void)out_size;
    const float* x = (const float*)d_in[0];
    const float* gamma = (const float*)d_in[1];
    float* out = (float*)d_out;

    gram_kernel<<<GBLOCKS, 256>>>(x);
    affinity_kernel<<<BATCH, 256>>>();
    apply_kernel<<<BATCH * (NDIM / TILE3), 256>>>(x, gamma, out);
}